// round 6
// baseline (speedup 1.0000x reference)
#include <cuda_runtime.h>
#include <math.h>

#define H_DIM  2048
#define N_EXP  64
#define TOPK   8
#define KC     32      // K-chunk per smem stage
#define TILE_M 64      // tokens per block
#define NTHR   256

typedef unsigned long long u64;

// smem layout:
//  xsd: [64 rows][34 u64] duplicated x values ({x,x} per k), row stride 272B = 17408B
//  wsm: [32 k][64 floats], even/odd-quad permuted rows (256B each)   =  8192B
//  sc (epilogue reuse of xsd region): [64][65] floats = 16640B
#define XSD_STRIDE_U64 34
#define XSD_BYTES (TILE_M * XSD_STRIDE_U64 * 8)     // 17408
#define WSM_BYTES (KC * N_EXP * 4)                  // 8192
#define SMEM_BYTES (XSD_BYTES + WSM_BYTES)          // 25600

// W transposed once per launch into k-major scratch: Wt[k][e]
__device__ float g_Wt[H_DIM * N_EXP];

__global__ void transpose_w_kernel(const float* __restrict__ w) {
    int idx = blockIdx.x * 256 + threadIdx.x;   // idx = k*64 + e (e fastest -> coalesced writes)
    if (idx < H_DIM * N_EXP) {
        int k = idx >> 6;
        int e = idx & 63;
        g_Wt[idx] = w[(size_t)e * H_DIM + k];
    }
}

__device__ __forceinline__ u64 dup_f32(float a) {
    u64 d;
    asm("mov.b64 %0, {%1, %1};" : "=l"(d) : "f"(a));
    return d;
}

__device__ __forceinline__ void fma2(u64& acc, u64 a, u64 b) {
    asm("fma.rn.f32x2 %0, %1, %2, %0;" : "+l"(acc) : "l"(a), "l"(b));
}

__global__ __launch_bounds__(NTHR, 2) void moe_gate_kernel(
    const float* __restrict__ x,      // (T, H)
    float* __restrict__ out,
    int T, int two_outputs)
{
    __shared__ __align__(16) unsigned char smem_raw[SMEM_BYTES];
    u64*   xsd = (u64*)smem_raw;                         // [64][34] dup'd x
    char*  wsm = (char*)(smem_raw + XSD_BYTES);          // [32][256B] permuted W rows
    float* sc  = (float*)smem_raw;                       // [64][65] epilogue scores

    const int tid = threadIdx.x;
    const int r   = tid >> 3;    // 0..31
    const int c   = tid & 7;     // 0..7
    const int tm  = r * 2;       // 2 token rows per thread
    const int tn  = c * 8;       // 8 expert cols per thread
    const int blk = blockIdx.x;

    const float* xblk = x + (size_t)blk * TILE_M * H_DIM;

    // x-fill mapping: 4 threads per token row, each covers 8 k-values (2 float4)
    const int fmx = tid >> 2;           // token row 0..63
    const int fqx = (tid & 3) * 8;      // k offset 0,8,16,24

    // w-fill mapping precomputed per i: Q = tid + i*256; kw=Q>>4; ch=Q&15
    // store quad ch at permuted position (ch>>1) + ((ch&1)<<3)

    // accumulators: 2 tokens x 4 expert-pairs, packed f32x2
    u64 acc2[2][4];
    #pragma unroll
    for (int i = 0; i < 2; i++)
        #pragma unroll
        for (int j = 0; j < 4; j++) acc2[i][j] = 0ULL;

    // ---- prologue: prefetch first chunk into registers ----
    float4 px0, px1, pw[2];
    px0 = *(const float4*)(xblk + (size_t)fmx * H_DIM + fqx);
    px1 = *(const float4*)(xblk + (size_t)fmx * H_DIM + fqx + 4);
    #pragma unroll
    for (int i = 0; i < 2; i++) {
        int Q  = tid + i * 256;
        int kw = Q >> 4, ch = Q & 15;
        pw[i] = *(const float4*)&g_Wt[(size_t)kw * N_EXP + ch * 4];
    }

    for (int k0 = 0; k0 < H_DIM; k0 += KC) {
        // ---- store prefetched chunk to smem ----
        {
            u64* xrow = &xsd[fmx * XSD_STRIDE_U64 + fqx];
            ulonglong2 t;
            t.x = dup_f32(px0.x); t.y = dup_f32(px0.y); *(ulonglong2*)&xrow[0] = t;
            t.x = dup_f32(px0.z); t.y = dup_f32(px0.w); *(ulonglong2*)&xrow[2] = t;
            t.x = dup_f32(px1.x); t.y = dup_f32(px1.y); *(ulonglong2*)&xrow[4] = t;
            t.x = dup_f32(px1.z); t.y = dup_f32(px1.w); *(ulonglong2*)&xrow[6] = t;
        }
        #pragma unroll
        for (int i = 0; i < 2; i++) {
            int Q  = tid + i * 256;
            int kw = Q >> 4, ch = Q & 15;
            int pos = (ch >> 1) + ((ch & 1) << 3);
            *(float4*)(wsm + kw * 256 + pos * 16) = pw[i];
        }
        __syncthreads();

        // ---- prefetch next chunk (overlaps with compute below) ----
        int kn = k0 + KC;
        if (kn < H_DIM) {
            px0 = *(const float4*)(xblk + (size_t)fmx * H_DIM + kn + fqx);
            px1 = *(const float4*)(xblk + (size_t)fmx * H_DIM + kn + fqx + 4);
            #pragma unroll
            for (int i = 0; i < 2; i++) {
                int Q  = tid + i * 256;
                int kw = Q >> 4, ch = Q & 15;
                pw[i] = *(const float4*)&g_Wt[(size_t)(kn + kw) * N_EXP + ch * 4];
            }
        }

        // ---- compute: per k2: 2 A-LDS.128 + 4 B-LDS.128 + 16 FFMA2 ----
        #pragma unroll
        for (int kk = 0; kk < KC; kk += 2) {
            ulonglong2 A0 = *(const ulonglong2*)&xsd[(tm + 0) * XSD_STRIDE_U64 + kk];
            ulonglong2 A1 = *(const ulonglong2*)&xsd[(tm + 1) * XSD_STRIDE_U64 + kk];
            #pragma unroll
            for (int s = 0; s < 2; s++) {
                const char* wrow = wsm + (kk + s) * 256;
                ulonglong2 BL = *(const ulonglong2*)(wrow + c * 16);
                ulonglong2 BH = *(const ulonglong2*)(wrow + 128 + c * 16);
                u64 a0 = s ? A0.y : A0.x;
                u64 a1 = s ? A1.y : A1.x;
                fma2(acc2[0][0], a0, BL.x); fma2(acc2[0][1], a0, BL.y);
                fma2(acc2[0][2], a0, BH.x); fma2(acc2[0][3], a0, BH.y);
                fma2(acc2[1][0], a1, BL.x); fma2(acc2[1][1], a1, BL.y);
                fma2(acc2[1][2], a1, BH.x); fma2(acc2[1][3], a1, BH.y);
            }
        }
        __syncthreads();
    }

    // ---- epilogue: unpack scores to smem, then 1 thread per token ----
    #pragma unroll
    for (int i = 0; i < 2; i++)
        #pragma unroll
        for (int j = 0; j < 4; j++) {
            float lo, hi;
            asm("mov.b64 {%0, %1}, %2;" : "=f"(lo), "=f"(hi) : "l"(acc2[i][j]));
            sc[(tm + i) * (N_EXP + 1) + tn + 2 * j]     = lo;
            sc[(tm + i) * (N_EXP + 1) + tn + 2 * j + 1] = hi;
        }
    __syncthreads();

    if (tid < TILE_M) {
        const float* row = &sc[tid * (N_EXP + 1)];

        float mx = row[0];
        #pragma unroll
        for (int e = 1; e < N_EXP; e++) mx = fmaxf(mx, row[e]);

        // top-8 on raw scores (softmax monotonic; denominator cancels under renorm).
        // Strict '>' => earliest index wins ties (matches lax.top_k).
        unsigned long long used = 0ULL;
        int   idxs[TOPK];
        float vals[TOPK];
        #pragma unroll
        for (int k = 0; k < TOPK; k++) {
            float best = -INFINITY;
            int   bi   = 0;
            for (int e = 0; e < N_EXP; e++) {
                if (!((used >> e) & 1ULL)) {
                    float v = row[e];
                    if (v > best) { best = v; bi = e; }
                }
            }
            used |= 1ULL << bi;
            idxs[k] = bi;
            vals[k] = best;
        }

        float ew[TOPK];
        float sumw = 0.0f;
        #pragma unroll
        for (int k = 0; k < TOPK; k++) {
            ew[k] = expf(vals[k] - mx);
            sumw += ew[k];
        }
        float inv = 1.0f / sumw;

        size_t t = (size_t)blk * TILE_M + tid;
        if (two_outputs) {
            #pragma unroll
            for (int k = 0; k < TOPK; k++) {
                out[t * TOPK + k] = (float)idxs[k];
                out[(size_t)T * TOPK + t * TOPK + k] = ew[k] * inv;
            }
        } else {
            #pragma unroll
            for (int k = 0; k < TOPK; k++)
                out[t * TOPK + k] = ew[k] * inv;
        }
    }
}

extern "C" void kernel_launch(void* const* d_in, const int* in_sizes, int n_in,
                              void* d_out, int out_size) {
    const float* x = (const float*)d_in[0];   // hidden_states (B,S,H) flattened
    const float* w = (const float*)d_in[1];   // weight (E,H)
    int T = in_sizes[0] / H_DIM;              // 16384
    int two = (out_size >= 2 * T * TOPK) ? 1 : 0;

    transpose_w_kernel<<<(H_DIM * N_EXP + 255) / 256, 256>>>(w);

    int grid = T / TILE_M;                    // 256
    moe_gate_kernel<<<grid, NTHR>>>(x, (float*)d_out, T, two);
}